// round 11
// baseline (speedup 1.0000x reference)
#include <cuda_runtime.h>

// Problem: B=2, 128^3 grid, C=3, 7 scaling-and-squaring steps.
#define D 128
#define DMASK 127
#define D3 (D * D * D)          // 2097152
#define NVOX (2 * D3)           // 4194304 voxels (B=2)
#define NT 256
#define NB2 (D3 / NT)           // 8192 blocks; each thread does batch0+batch1 voxel

// Two SoA ping-pong buffers, 48 MB each. Layout: [comp][b*D3 + x*D*D + y*D + z].
__device__ float gA[3 * NVOX];
__device__ float gB[3 * NVOX];

// ---------------------------------------------------------------------------
// Transpose + scale: AoS dvf (float3/voxel) -> SoA planes in gA, * 2^-7.
// ---------------------------------------------------------------------------
__global__ __launch_bounds__(256) void transpose_scale_kernel(
    const float4* __restrict__ in4)
{
    const int i = blockIdx.x * 256 + threadIdx.x;        // i < 3*NVOX/4
    const float s = 1.0f / 128.0f;                       // 2^-7, exact
    float4 v = in4[i];
    float vals[4] = {v.x, v.y, v.z, v.w};
    const int f = 4 * i;
    #pragma unroll
    for (int j = 0; j < 4; j++) {
        const int ff  = f + j;
        const int vox = ff / 3;
        const int c   = ff - 3 * vox;
        gA[c * NVOX + vox] = s * vals[j];
    }
}

// ---------------------------------------------------------------------------
// One squaring step. Each thread handles TWO independent voxels: the same
// (x,y,z) in batch 0 and batch 1. The two streams share the spatial decode
// and interleave their memory ops for latency hiding.
// SRC: 1 = gA, 2 = gB.   DST: 0 = external AoS, 1 = gA, 2 = gB.
// ---------------------------------------------------------------------------
template <int SRC, int DST>
__global__ __launch_bounds__(NT, 5) void step_soa2_kernel(
    float* __restrict__ ext_out)
{
    const float* __restrict__ sx = (SRC == 1) ? gA : gB;
    const float* __restrict__ sy = sx + NVOX;
    const float* __restrict__ sz = sx + 2 * NVOX;

    const int gid = blockIdx.x * NT + threadIdx.x;   // < D3

    // Shared spatial decode for both batches.
    const int z = gid & DMASK;
    const int y = (gid >> 7) & DMASK;
    const int x = (gid >> 14) & DMASK;
    const float xf = (float)x, yf = (float)y, zf = (float)z;

    #pragma unroll
    for (int s = 0; s < 2; s++) {
        const int idx = gid + s * D3;
        const int bbase = s * D3;

        // Center displacement (coalesced).
        const float vx = __ldg(sx + idx);
        const float vy = __ldg(sy + idx);
        const float vz = __ldg(sz + idx);

        const float lx = xf + vx;
        const float ly = yf + vy;
        const float lz = zf + vz;

        const float fx = floorf(lx), fy = floorf(ly), fz = floorf(lz);
        const float wx1 = lx - fx, wy1 = ly - fy, wz1 = lz - fz;
        const float wx0 = 1.0f - wx1, wy0 = 1.0f - wy1, wz0 = 1.0f - wz1;

        const int ix = (int)fx, iy = (int)fy, iz = (int)fz;

        // Clip corner indices; weights stay unclipped (matches reference).
        const int ix0 = min(max(ix,     0), DMASK);
        const int ix1 = min(max(ix + 1, 0), DMASK);
        const int iy0 = min(max(iy,     0), DMASK);
        const int iy1 = min(max(iy + 1, 0), DMASK);
        const int iz0 = min(max(iz,     0), DMASK);
        const int iz1 = min(max(iz + 1, 0), DMASK);

        const int X0 = bbase + (ix0 << 14);
        const int X1 = bbase + (ix1 << 14);
        const int Y0 = iy0 << 7;
        const int Y1 = iy1 << 7;

        const float w00 = wx0 * wy0;
        const float w01 = wx0 * wy1;
        const float w10 = wx1 * wy0;
        const float w11 = wx1 * wy1;

        float ax = 0.0f, ay = 0.0f, az = 0.0f;

        #define CORNER(W, LIN)                                                \
            do {                                                              \
                const float w_ = (W);                                         \
                const int   l_ = (LIN);                                       \
                ax = fmaf(w_, __ldg(sx + l_), ax);                            \
                ay = fmaf(w_, __ldg(sy + l_), ay);                            \
                az = fmaf(w_, __ldg(sz + l_), az);                            \
            } while (0)

        CORNER(w00 * wz0, X0 + Y0 + iz0);
        CORNER(w00 * wz1, X0 + Y0 + iz1);
        CORNER(w01 * wz0, X0 + Y1 + iz0);
        CORNER(w01 * wz1, X0 + Y1 + iz1);
        CORNER(w10 * wz0, X1 + Y0 + iz0);
        CORNER(w10 * wz1, X1 + Y0 + iz1);
        CORNER(w11 * wz0, X1 + Y1 + iz0);
        CORNER(w11 * wz1, X1 + Y1 + iz1);
        #undef CORNER

        const float ox = vx + ax;
        const float oy = vy + ay;
        const float oz = vz + az;

        if (DST == 0) {
            // Final step: AoS float3 into d_out.
            float* o = ext_out + 3 * idx;
            o[0] = ox; o[1] = oy; o[2] = oz;
        } else {
            float* dx = (DST == 1) ? gA : gB;
            dx[idx]            = ox;
            dx[NVOX + idx]     = oy;
            dx[2 * NVOX + idx] = oz;
        }
    }
}

extern "C" void kernel_launch(void* const* d_in, const int* in_sizes, int n_in,
                              void* d_out, int out_size)
{
    const float4* dvf4 = (const float4*)d_in[0];
    float* out = (float*)d_out;

    // AoS dvf -> scaled SoA in gA (ddf0 = dvf * 2^-7, exact).
    transpose_scale_kernel<<<(3 * NVOX / 4) / 256, 256>>>(dvf4);

    // 7 squaring steps, ping-pong; final step writes AoS into d_out.
    step_soa2_kernel<1, 2><<<NB2, NT>>>(nullptr);  // 1: A -> B
    step_soa2_kernel<2, 1><<<NB2, NT>>>(nullptr);  // 2: B -> A
    step_soa2_kernel<1, 2><<<NB2, NT>>>(nullptr);  // 3: A -> B
    step_soa2_kernel<2, 1><<<NB2, NT>>>(nullptr);  // 4: B -> A
    step_soa2_kernel<1, 2><<<NB2, NT>>>(nullptr);  // 5: A -> B
    step_soa2_kernel<2, 1><<<NB2, NT>>>(nullptr);  // 6: B -> A
    step_soa2_kernel<1, 0><<<NB2, NT>>>(out);      // 7: A -> d_out
}